// round 15
// baseline (speedup 1.0000x reference)
#include <cuda_runtime.h>
#include <cuda_fp16.h>
#include <cstdint>

// out[b,i,j,m,n] = <q_norm[b,i,m,:], s_norm[b,j,n,:]>
// q,s: [4,25,128,64] fp32; out: [4,25,25,128,128] fp32
static constexpr int B_ = 4, I_ = 25, M_ = 128, K_ = 64;
static constexpr int NROWS = B_ * I_ * M_;          // 12800 rows per tensor
static constexpr int NTILES = B_ * I_ * I_;         // 2500
static constexpr int NC = 304;                      // persistent CTAs (2/SM x 152 SMs)

static constexpr int PITCH_H = 72;                  // halves per smem row (144 B)
static constexpr int TILE_BYTES = M_ * PITCH_H * 2; // 18432
static constexpr int SMEM_BYTES = 4 * TILE_BYTES;   // Q[2] + S[2] = 73728

// Pre-normalized fp16 operands
__device__ __half d_qh[NROWS * K_];
__device__ __half d_sh[NROWS * K_];

__device__ __forceinline__ uint32_t smem_u32(const void* p) {
    uint32_t a;
    asm("{ .reg .u64 t; cvta.to.shared.u64 t, %1; cvt.u32.u64 %0, t; }" : "=r"(a) : "l"(p));
    return a;
}

__device__ __forceinline__ void ldsm_x4(uint32_t* r, uint32_t addr) {
    asm volatile("ldmatrix.sync.aligned.m8n8.x4.shared.b16 {%0,%1,%2,%3}, [%4];"
                 : "=r"(r[0]), "=r"(r[1]), "=r"(r[2]), "=r"(r[3]) : "r"(addr));
}

__device__ __forceinline__ void mma_f16(float* c, const uint32_t* a, const uint32_t* b) {
    asm volatile(
        "mma.sync.aligned.m16n8k16.row.col.f32.f16.f16.f32 "
        "{%0,%1,%2,%3}, {%4,%5,%6,%7}, {%8,%9}, {%0,%1,%2,%3};"
        : "+f"(c[0]), "+f"(c[1]), "+f"(c[2]), "+f"(c[3])
        : "r"(a[0]), "r"(a[1]), "r"(a[2]), "r"(a[3]), "r"(b[0]), "r"(b[1]));
}

__device__ __forceinline__ void cp16(uint32_t dst, const void* src) {
    asm volatile("cp.async.cg.shared.global [%0], [%1], 16;" :: "r"(dst), "l"(src));
}
__device__ __forceinline__ void cp_commit() {
    asm volatile("cp.async.commit_group;" ::: "memory");
}
__device__ __forceinline__ void cp_wait0() {
    asm volatile("cp.async.wait_group 0;" ::: "memory");
}

// sigma involution within each 32-row block: x=8nt+2tg+e -> 8tg+2nt+e
__device__ __forceinline__ int sigma32(int x) {
    return ((x & 6) << 2) | ((x >> 2) & 6) | (x & 1);
}

// Stage one 128x64 fp16 tile into padded smem (Q: identity row order).
__device__ __forceinline__ void stage_q(uint32_t dstBase, const __half* srcTile, int tid) {
    #pragma unroll
    for (int u = 0; u < 4; u++) {
        const int chunk = u * 256 + tid;         // 0..1023 16B-chunks
        const int row = chunk >> 3;
        const int c16 = chunk & 7;
        cp16(dstBase + (uint32_t)row * (PITCH_H * 2) + c16 * 16,
             srcTile + (size_t)row * K_ + c16 * 8);
    }
}
// Stage S tile with sigma-permuted rows (within each 32-row block).
__device__ __forceinline__ void stage_s(uint32_t dstBase, const __half* srcTile, int tid) {
    #pragma unroll
    for (int u = 0; u < 4; u++) {
        const int chunk = u * 256 + tid;
        const int row = chunk >> 3;
        const int c16 = chunk & 7;
        const int srow = (row & ~31) | sigma32(row & 31);
        cp16(dstBase + (uint32_t)row * (PITCH_H * 2) + c16 * 16,
             srcTile + (size_t)srow * K_ + c16 * 8);
    }
}

// ---------------- Kernel 1: normalize to fp16 (2 threads per row) ----------------
__global__ void __launch_bounds__(256)
normalize_kernel(const float* __restrict__ q, const float* __restrict__ s) {
    const int gid = blockIdx.x * 256 + threadIdx.x;   // 0..51199
    const int r = gid >> 1;
    const int half = gid & 1;
    const bool isQ = r < NROWS;
    const int rr = isQ ? r : r - NROWS;
    const float4* src = (const float4*)((isQ ? q : s) + (size_t)rr * K_) + half * 8;
    __half* dst = (isQ ? d_qh : d_sh) + (size_t)rr * K_ + half * 32;

    float4 v[8];
    float sum = 0.f;
    #pragma unroll
    for (int u = 0; u < 8; u++) {
        v[u] = src[u];
        sum = fmaf(v[u].x, v[u].x, sum);
        sum = fmaf(v[u].y, v[u].y, sum);
        sum = fmaf(v[u].z, v[u].z, sum);
        sum = fmaf(v[u].w, v[u].w, sum);
    }
    sum += __shfl_xor_sync(0xffffffffu, sum, 1);
    const float inv = 1.0f / fmaxf(sqrtf(sum), 1e-12f);
    #pragma unroll
    for (int u = 0; u < 4; u++) {
        const float4 p = v[2 * u], w = v[2 * u + 1];
        __half2 h0 = __floats2half2_rn(p.x * inv, p.y * inv);
        __half2 h1 = __floats2half2_rn(p.z * inv, p.w * inv);
        __half2 h2 = __floats2half2_rn(w.x * inv, w.y * inv);
        __half2 h3 = __floats2half2_rn(w.z * inv, w.w * inv);
        uint4 o;
        o.x = *(uint32_t*)&h0; o.y = *(uint32_t*)&h1;
        o.z = *(uint32_t*)&h2; o.w = *(uint32_t*)&h3;
        *(uint4*)(dst + u * 8) = o;
    }
}

// ---------------- Kernel 2: persistent GEMM, sigma-direct STG.128 epilogue ----------------
__global__ void __launch_bounds__(256, 2)
cosine_gemm_kernel(float* __restrict__ out) {
    extern __shared__ __half sm[];
    const uint32_t qBase = smem_u32(sm);                 // Q double buffer [2]
    const uint32_t sBase = qBase + 2 * TILE_BYTES;       // S double buffer [2]

    const int tid = threadIdx.x;
    const int cidx = blockIdx.x;

    const int t0 = (int)((long long)cidx * NTILES / NC);
    const int t1 = (int)((long long)(cidx + 1) * NTILES / NC);
    if (t0 >= t1) return;

    const int wid = tid >> 5;
    const int lane = tid & 31;
    const int g = lane >> 2;
    const int tg = lane & 3;
    const int mwBase = (wid & 1) * 64;
    const int nwBase = (wid >> 1) * 32;
    const int slot = lane >> 3;
    const int l7 = lane & 7;

    const uint32_t baseArel =
        ((uint32_t)(mwBase + (slot & 1) * 8 + l7) * PITCH_H + (slot >> 1) * 8) * 2;
    const uint32_t baseBrel =
        ((uint32_t)(nwBase + (slot >> 1) * 8 + l7) * PITCH_H + (slot & 1) * 8) * 2;

    int bi = t0 / I_;
    stage_q(qBase, d_qh + (size_t)bi * (M_ * K_), tid);
    stage_s(sBase, d_sh + (size_t)((bi / I_) * I_ + (t0 % I_)) * (M_ * K_), tid);
    cp_commit();
    cp_wait0();
    __syncthreads();

    int qcur = 0;

    for (int t = t0; t < t1; t++) {
        const int sp = (t - t0) & 1;
        bool qflip = false;

        if (t + 1 < t1) {
            const int nbi = (t + 1) / I_;
            if (nbi != bi) {
                stage_q(qBase + (qcur ^ 1) * TILE_BYTES,
                        d_qh + (size_t)nbi * (M_ * K_), tid);
                qflip = true;
            }
            stage_s(sBase + (sp ^ 1) * TILE_BYTES,
                    d_sh + (size_t)((nbi / I_) * I_ + ((t + 1) % I_)) * (M_ * K_), tid);
            cp_commit();
        }

        const uint32_t baseA = qBase + qcur * TILE_BYTES + baseArel;
        const uint32_t baseB = sBase + sp * TILE_BYTES + baseBrel;

        float c[4][4][4];
        #pragma unroll
        for (int mt = 0; mt < 4; mt++)
            #pragma unroll
            for (int nt = 0; nt < 4; nt++)
                #pragma unroll
                for (int e = 0; e < 4; e++)
                    c[mt][nt][e] = 0.f;

        #pragma unroll
        for (int ks = 0; ks < 4; ks++) {
            const uint32_t kOff = (uint32_t)ks * 16 * 2;

            uint32_t a[4][4];
            #pragma unroll
            for (int mt = 0; mt < 4; mt++)
                ldsm_x4(a[mt], baseA + (uint32_t)mt * 16 * PITCH_H * 2 + kOff);

            uint32_t bf[2][4];
            #pragma unroll
            for (int np = 0; np < 2; np++)
                ldsm_x4(bf[np], baseB + (uint32_t)np * 16 * PITCH_H * 2 + kOff);

            #pragma unroll
            for (int mt = 0; mt < 4; mt++)
                #pragma unroll
                for (int nt = 0; nt < 4; nt++)
                    mma_f16(c[mt][nt], a[mt], &bf[nt >> 1][(nt & 1) * 2]);
        }

        // ---- Epilogue: sigma layout -> lane (g,tg) holds 8 output-contiguous
        // floats per row. Direct STG.128 x2 per row. (Layout validated R11/R12.)
        float* gO = out + (size_t)t * (M_ * M_);
        #pragma unroll
        for (int mt = 0; mt < 4; mt++) {
            const int r0 = mwBase + mt * 16 + g;
            float* p0 = gO + (size_t)r0 * M_ + nwBase + 8 * tg;
            float* p1 = gO + (size_t)(r0 + 8) * M_ + nwBase + 8 * tg;
            *(float4*)p0       = make_float4(c[mt][0][0], c[mt][0][1], c[mt][1][0], c[mt][1][1]);
            *(float4*)(p0 + 4) = make_float4(c[mt][2][0], c[mt][2][1], c[mt][3][0], c[mt][3][1]);
            *(float4*)p1       = make_float4(c[mt][0][2], c[mt][0][3], c[mt][1][2], c[mt][1][3]);
            *(float4*)(p1 + 4) = make_float4(c[mt][2][2], c[mt][2][3], c[mt][3][2], c[mt][3][3]);
        }

        if (t + 1 < t1) {
            cp_wait0();
            __syncthreads();
            if (qflip) { qcur ^= 1; bi = (t + 1) / I_; }
        }
    }
}

extern "C" void kernel_launch(void* const* d_in, const int* in_sizes, int n_in,
                              void* d_out, int out_size) {
    const float* query   = (const float*)d_in[0];
    const float* support = (const float*)d_in[1];
    float* out = (float*)d_out;

    cudaFuncSetAttribute(cosine_gemm_kernel,
                         cudaFuncAttributeMaxDynamicSharedMemorySize, SMEM_BYTES);

    normalize_kernel<<<200, 256>>>(query, support);
    cosine_gemm_kernel<<<NC, 256, SMEM_BYTES>>>(out);
}

// round 16
// speedup vs baseline: 1.3265x; 1.3265x over previous
#include <cuda_runtime.h>
#include <cuda_fp16.h>
#include <cstdint>

// out[b,i,j,m,n] = <q_norm[b,i,m,:], s_norm[b,j,n,:]>
// q,s: [4,25,128,64] fp32; out: [4,25,25,128,128] fp32
static constexpr int B_ = 4, I_ = 25, M_ = 128, K_ = 64;
static constexpr int NROWS = B_ * I_ * M_;          // 12800 rows per tensor
static constexpr int NTILES = B_ * I_ * I_;         // 2500
static constexpr int NC = 304;                      // persistent CTAs (2/SM x 152 SMs)

static constexpr int PITCH_H = 72;                  // halves per smem row (144 B)
static constexpr int TILE_BYTES = M_ * PITCH_H * 2; // 18432
static constexpr int SMEM_BYTES = 4 * TILE_BYTES;   // Q[2] + S[2] = 73728

// Pre-normalized fp16 operands (phase 1 of the fused kernel)
__device__ __half d_qh[NROWS * K_];
__device__ __half d_sh[NROWS * K_];
__device__ int g_bar;                               // reset via cudaMemsetAsync each launch

__device__ __forceinline__ uint32_t smem_u32(const void* p) {
    uint32_t a;
    asm("{ .reg .u64 t; cvta.to.shared.u64 t, %1; cvt.u32.u64 %0, t; }" : "=r"(a) : "l"(p));
    return a;
}

__device__ __forceinline__ void ldsm_x4(uint32_t* r, uint32_t addr) {
    asm volatile("ldmatrix.sync.aligned.m8n8.x4.shared.b16 {%0,%1,%2,%3}, [%4];"
                 : "=r"(r[0]), "=r"(r[1]), "=r"(r[2]), "=r"(r[3]) : "r"(addr));
}

__device__ __forceinline__ void mma_f16(float* c, const uint32_t* a, const uint32_t* b) {
    asm volatile(
        "mma.sync.aligned.m16n8k16.row.col.f32.f16.f16.f32 "
        "{%0,%1,%2,%3}, {%4,%5,%6,%7}, {%8,%9}, {%0,%1,%2,%3};"
        : "+f"(c[0]), "+f"(c[1]), "+f"(c[2]), "+f"(c[3])
        : "r"(a[0]), "r"(a[1]), "r"(a[2]), "r"(a[3]), "r"(b[0]), "r"(b[1]));
}

__device__ __forceinline__ void cp16(uint32_t dst, const void* src) {
    asm volatile("cp.async.cg.shared.global [%0], [%1], 16;" :: "r"(dst), "l"(src));
}
__device__ __forceinline__ void cp_commit() {
    asm volatile("cp.async.commit_group;" ::: "memory");
}
__device__ __forceinline__ void cp_wait0() {
    asm volatile("cp.async.wait_group 0;" ::: "memory");
}
__device__ __forceinline__ int ld_cg(const int* p) {
    int v;
    asm volatile("ld.global.cg.b32 %0, [%1];" : "=r"(v) : "l"(p));
    return v;
}

// Stage one 128x64 fp16 tile (row-major, 128 B/row) into padded smem via cp.async.
__device__ __forceinline__ void stage_tile(uint32_t dstBase, const __half* srcTile, int tid) {
    #pragma unroll
    for (int u = 0; u < 4; u++) {
        const int chunk = u * 256 + tid;         // 0..1023 16B-chunks
        const int row = chunk >> 3;
        const int c16 = chunk & 7;
        cp16(dstBase + (uint32_t)row * (PITCH_H * 2) + c16 * 16,
             srcTile + (size_t)row * K_ + c16 * 8);
    }
}

// ---------------- Fused persistent kernel ----------------
__global__ void __launch_bounds__(256, 2)
cosine_fused_kernel(const float* __restrict__ q, const float* __restrict__ s,
                    float* __restrict__ out) {
    extern __shared__ __half sm[];
    const uint32_t qBase = smem_u32(sm);                 // Q double buffer [2]
    const uint32_t sBase = qBase + 2 * TILE_BYTES;       // S double buffer [2]

    const int tid = threadIdx.x;
    const int cidx = blockIdx.x;

    // ===== Phase 1: normalize -> fp16 (2 threads per row, one task/thread) =====
    {
        const int gid = cidx * 256 + tid;                // 0..77823; tasks: 0..51199
        if (gid < 4 * NROWS) {
            const int r = gid >> 1;
            const int half = gid & 1;
            const bool isQ = r < NROWS;
            const int rr = isQ ? r : r - NROWS;
            const float4* src = (const float4*)((isQ ? q : s) + (size_t)rr * K_) + half * 8;
            __half* dst = (isQ ? d_qh : d_sh) + (size_t)rr * K_ + half * 32;

            float4 v[8];
            float sum = 0.f;
            #pragma unroll
            for (int u = 0; u < 8; u++) {
                v[u] = src[u];
                sum = fmaf(v[u].x, v[u].x, sum);
                sum = fmaf(v[u].y, v[u].y, sum);
                sum = fmaf(v[u].z, v[u].z, sum);
                sum = fmaf(v[u].w, v[u].w, sum);
            }
            sum += __shfl_xor_sync(0xffffffffu, sum, 1);
            const float inv = 1.0f / fmaxf(sqrtf(sum), 1e-12f);
            #pragma unroll
            for (int u = 0; u < 4; u++) {
                const float4 p = v[2 * u], w = v[2 * u + 1];
                __half2 h0 = __floats2half2_rn(p.x * inv, p.y * inv);
                __half2 h1 = __floats2half2_rn(p.z * inv, p.w * inv);
                __half2 h2 = __floats2half2_rn(w.x * inv, w.y * inv);
                __half2 h3 = __floats2half2_rn(w.z * inv, w.w * inv);
                uint4 o;
                o.x = *(uint32_t*)&h0; o.y = *(uint32_t*)&h1;
                o.z = *(uint32_t*)&h2; o.w = *(uint32_t*)&h3;
                *(uint4*)(dst + u * 8) = o;
            }
        }
    }

    // ===== Grid barrier: one atomic arrive, then cheap ld.cg polling =====
    __syncthreads();
    if (tid == 0) {
        __threadfence();
        atomicAdd(&g_bar, 1);
        while (ld_cg(&g_bar) < NC) { __nanosleep(64); }
        __threadfence();
    }
    __syncthreads();

    // ===== Phase 2: persistent grouped GEMM (R6 body verbatim) =====
    const int t0 = (int)((long long)cidx * NTILES / NC);
    const int t1 = (int)((long long)(cidx + 1) * NTILES / NC);
    if (t0 >= t1) return;

    const int wid = tid >> 5;
    const int lane = tid & 31;
    const int g = lane >> 2;
    const int tg = lane & 3;
    const int mwBase = (wid & 1) * 64;
    const int nwBase = (wid >> 1) * 32;
    const int slot = lane >> 3;
    const int l7 = lane & 7;

    const uint32_t baseArel =
        ((uint32_t)(mwBase + (slot & 1) * 8 + l7) * PITCH_H + (slot >> 1) * 8) * 2;
    const uint32_t baseBrel =
        ((uint32_t)(nwBase + (slot >> 1) * 8 + l7) * PITCH_H + (slot & 1) * 8) * 2;

    int bi = t0 / I_;
    stage_tile(qBase, d_qh + (size_t)bi * (M_ * K_), tid);
    stage_tile(sBase, d_sh + (size_t)((bi / I_) * I_ + (t0 % I_)) * (M_ * K_), tid);
    cp_commit();
    cp_wait0();
    __syncthreads();

    int qcur = 0;

    for (int t = t0; t < t1; t++) {
        const int sp = (t - t0) & 1;
        bool qflip = false;

        if (t + 1 < t1) {
            const int nbi = (t + 1) / I_;
            if (nbi != bi) {
                stage_tile(qBase + (qcur ^ 1) * TILE_BYTES,
                           d_qh + (size_t)nbi * (M_ * K_), tid);
                qflip = true;
            }
            stage_tile(sBase + (sp ^ 1) * TILE_BYTES,
                       d_sh + (size_t)((nbi / I_) * I_ + ((t + 1) % I_)) * (M_ * K_), tid);
            cp_commit();
        }

        const uint32_t baseA = qBase + qcur * TILE_BYTES + baseArel;
        const uint32_t baseB = sBase + sp * TILE_BYTES + baseBrel;

        float c[4][4][4];
        #pragma unroll
        for (int mt = 0; mt < 4; mt++)
            #pragma unroll
            for (int nt = 0; nt < 4; nt++)
                #pragma unroll
                for (int e = 0; e < 4; e++)
                    c[mt][nt][e] = 0.f;

        #pragma unroll
        for (int ks = 0; ks < 4; ks++) {
            const uint32_t kOff = (uint32_t)ks * 16 * 2;

            uint32_t a[4][4];
            #pragma unroll
            for (int mt = 0; mt < 4; mt++)
                ldsm_x4(a[mt], baseA + (uint32_t)mt * 16 * PITCH_H * 2 + kOff);

            uint32_t bf[2][4];
            #pragma unroll
            for (int np = 0; np < 2; np++)
                ldsm_x4(bf[np], baseB + (uint32_t)np * 16 * PITCH_H * 2 + kOff);

            #pragma unroll
            for (int mt = 0; mt < 4; mt++)
                #pragma unroll
                for (int nt = 0; nt < 4; nt++)
                    mma_f16(c[mt][nt], a[mt], &bf[nt >> 1][(nt & 1) * 2]);
        }

        // Epilogue: float2 stores (quad-contiguous 32B sectors) — R6 pattern
        float* gO = out + (size_t)t * (M_ * M_);
        #pragma unroll
        for (int mt = 0; mt < 4; mt++) {
            const int r0 = mwBase + mt * 16 + g;
            #pragma unroll
            for (int nt = 0; nt < 4; nt++) {
                const int col = nwBase + nt * 8 + tg * 2;
                *(float2*)(gO + (size_t)r0 * M_ + col)       = make_float2(c[mt][nt][0], c[mt][nt][1]);
                *(float2*)(gO + (size_t)(r0 + 8) * M_ + col) = make_float2(c[mt][nt][2], c[mt][nt][3]);
            }
        }

        if (t + 1 < t1) {
            cp_wait0();
            __syncthreads();
            if (qflip) { qcur ^= 1; bi = (t + 1) / I_; }
        }
    }
}

extern "C" void kernel_launch(void* const* d_in, const int* in_sizes, int n_in,
                              void* d_out, int out_size) {
    const float* query   = (const float*)d_in[0];
    const float* support = (const float*)d_in[1];
    float* out = (float*)d_out;

    cudaFuncSetAttribute(cosine_fused_kernel,
                         cudaFuncAttributeMaxDynamicSharedMemorySize, SMEM_BYTES);

    void* barAddr = nullptr;
    cudaGetSymbolAddress(&barAddr, g_bar);
    cudaMemsetAsync(barAddr, 0, sizeof(int));

    cosine_fused_kernel<<<NC, 256, SMEM_BYTES>>>(query, support, out);
}